// round 3
// baseline (speedup 1.0000x reference)
#include <cuda_runtime.h>
#include <math.h>

#define NB 16
#define NA 5
#define NH 96
#define NW 96
#define NHW 9216
#define TT 50
#define ROWS 3
#define TPB (ROWS * NW)              // 288 threads
#define DENSE_BX (NA * NH / ROWS)    // 160 dense blocks per batch
#define TOTAL_BLOCKS ((DENSE_BX + 1) * NB)   // 2576

__constant__ float c_aw[NA] = {1.3221f, 3.19275f, 5.05587f, 9.47112f, 11.2364f};
__constant__ float c_ah[NA] = {1.73145f, 4.00944f, 8.09892f, 4.84053f, 10.0071f};

__device__ double   g_acc;
__device__ unsigned g_done;

__device__ __forceinline__ float sigmoidf_(float x) { return 1.f / (1.f + __expf(-x)); }

__global__ void init_kernel()
{
    g_acc = 0.0;
    g_done = 0u;
}

// ---------------------------------------------------------------------------
// One fused kernel. grid = (161, 16), block = 288.
//   blockIdx.x < 160 : dense no-object term for 3 grid rows of one anchor
//   blockIdx.x == 160: sparse per-target loss for batch blockIdx.y
// Last block to finish writes the final scalar (done-counter pattern).
// ---------------------------------------------------------------------------
__global__ void __launch_bounds__(TPB)
fused_kernel(const float* __restrict__ out, const float* __restrict__ tgt,
             float* __restrict__ res)
{
    __shared__ float4 sA[TT + 8];     // gt extents: xlo, xhi, ylo, yhi
    __shared__ float  sbz[TT + 8];    // 0.6 * gt area
    __shared__ int    sidx[TT];
    __shared__ int    smask[2];
    __shared__ int    s_cnt;
    __shared__ float  wsum[9];
    __shared__ double s_acc;

    const int b = blockIdx.y;
    const int tid = threadIdx.x;
    const float* tb = tgt + b * (TT * 6);

    double blockc = 0.0;   // this block's contribution (held by tid 0 at the end)

    if (blockIdx.x < DENSE_BX) {
        // =================== DENSE PATH ===================
        const int bx = blockIdx.x;
        const int a = bx >> 5;                 // bx / 32
        const int j0 = (bx & 31) * ROWS;
        const int jr = tid / NW;
        const int i = tid - jr * NW;
        const int j = j0 + jr;

        // issue output loads early (overlap with target parse)
        const float* op = out + ((b * NA + a) * 8) * NHW + j * NW + i;
        const float o0 = op[0];
        const float o1 = op[NHW];
        const float o2 = op[2 * NHW];
        const float o3 = op[3 * NHW];
        const float o4 = op[4 * NHW];

        if (tid == 0) s_cnt = 0;

        float xr = 1.f, gx = 0.f, gy = 0.f, gw = 0.f, gh = 0.f;
        if (tid < TT) {
            const float* tp = tb + tid * 6;
            xr = tp[1];
            gx = xr * NW;
            gy = tp[2] * NH;
            gw = tp[3] * NW;
            gh = tp[4] * NH;
        }
        if (tid < 64) {
            unsigned m = __ballot_sync(0xffffffffu, xr == 0.f);
            if ((tid & 31) == 0) smask[tid >> 5] = (int)m;
        }
        __syncthreads();
        const int nv = smask[0] ? (__ffs(smask[0]) - 1)
                                : (smask[1] ? 32 + __ffs(smask[1]) - 1 : TT);

        // y-band prune: iou>0.6 requires py in (gylo - gh/3, gyhi + gh/3).
        if (tid < nv) {
            const float ylo_g = gy - 0.5f * gh;
            const float yhi_g = gy + 0.5f * gh;
            const float ghd3 = gh * (1.f / 3.f);
            const bool keep = ((float)j0 < yhi_g + ghd3 + 0.5f) &&
                              ((float)(j0 + ROWS) > ylo_g - ghd3 - 0.5f);
            if (keep) {
                const int p = atomicAdd(&s_cnt, 1);
                sA[p] = make_float4(gx - 0.5f * gw, gx + 0.5f * gw, ylo_g, yhi_g);
                sbz[p] = 0.6f * (gw * gh);
            }
        }
        __syncthreads();
        const int cnt = s_cnt;
        if (tid < 4) {   // pad with never-firing dummies (iw < 0)
            sA[cnt + tid] = make_float4(1e30f, -1e30f, 1e30f, -1e30f);
            sbz[cnt + tid] = 0.f;
        }
        __syncthreads();

        const float px = sigmoidf_(o0) + (float)i;
        const float py = sigmoidf_(o1) + (float)j;
        const float pw = __expf(o2) * c_aw[a];
        const float ph = __expf(o3) * c_ah[a];

        const float xlo = px - 0.5f * pw, xhi = px + 0.5f * pw;
        const float ylo = py - 0.5f * ph, yhi = py + 0.5f * ph;
        const float c1 = 0.6f * (pw * ph);

        bool over = false;
        for (int k = 0; k < cnt; k += 4) {
            bool f = false;
#pragma unroll
            for (int u = 0; u < 4; u++) {
                const float4 a4 = sA[k + u];
                const float bz = sbz[k + u];
                const float iw = fminf(xhi, a4.y) - fmaxf(xlo, a4.x);
                const float ih = fminf(yhi, a4.w) - fmaxf(ylo, a4.z);
                f |= (fminf(iw, ih) > 0.f) &&
                     (fmaf(1.6f, iw * ih, -bz) > c1);
            }
            if (f) { over = true; break; }
        }

        const float conf = sigmoidf_(o4);
        float term = over ? 0.f : 0.5f * conf * conf;

#pragma unroll
        for (int off = 16; off > 0; off >>= 1)
            term += __shfl_down_sync(0xffffffffu, term, off);
        if ((tid & 31) == 0) wsum[tid >> 5] = term;
        __syncthreads();
        if (tid == 0) {
            float s = 0.f;
#pragma unroll
            for (int k = 0; k < 9; k++) s += wsum[k];
            blockc = (double)s;
        }
    } else {
        // =================== SPARSE PATH (one block per batch) ===================
        if (tid == 0) s_acc = 0.0;

        float xr = 1.f, tcls = 0.f, gx = 0.f, gy = 0.f, gw = 0.f, gh = 0.f, lr = 0.f;
        if (tid < TT) {
            const float* tp = tb + tid * 6;
            tcls = tp[0];
            xr = tp[1];
            gx = xr * NW;
            gy = tp[2] * NH;
            gw = tp[3] * NW;
            gh = tp[4] * NH;
            lr = tp[5];
        }
        if (tid < 64) {
            unsigned m = __ballot_sync(0xffffffffu, xr == 0.f);
            if ((tid & 31) == 0) smask[tid >> 5] = (int)m;
        }
        __syncthreads();
        const int nv = smask[0] ? (__ffs(smask[0]) - 1)
                                : (smask[1] ? 32 + __ffs(smask[1]) - 1 : TT);

        int bn = 0, gi = 0, gj = 0, idx = 0;
        if (tid < TT) {
            const float area = gw * gh;
            float best = -1.f;
#pragma unroll
            for (int k = 0; k < NA; k++) {
                const float inter = fminf(gw, c_aw[k]) * fminf(gh, c_ah[k]);
                const float iou = inter / (area + c_aw[k] * c_ah[k] - inter);
                if (iou > best) { best = iou; bn = k; }
            }
            gi = (int)gx;
            gj = (int)gy;
            idx = bn * NHW + gj * NW + gi;
            sidx[tid] = (tid < nv) ? idx : (-1 - tid);
            sA[tid] = make_float4(gx - 0.5f * gw, gx + 0.5f * gw,
                                  gy - 0.5f * gh, gy + 0.5f * gh);
            sbz[tid] = 0.6f * area;
        }
        __syncthreads();

        bool owner = tid < nv;
        if (owner)
            for (int t2 = tid + 1; t2 < nv; t2++)
                if (sidx[t2] == idx) { owner = false; break; }

        if (owner) {
            const float* op = out + ((b * NA + bn) * 8) * NHW + gj * NW + gi;
            const float o0 = op[0];
            const float o1 = op[NHW];
            const float o2 = op[2 * NHW];
            const float o3 = op[3 * NHW];
            const float o4 = op[4 * NHW];
            const float o5 = op[5 * NHW];
            const float o6 = op[6 * NHW];
            const float o7 = op[7 * NHW];

            const float x = sigmoidf_(o0);
            const float y = sigmoidf_(o1);
            const float px = x + (float)gi;
            const float py = y + (float)gj;
            const float pw = __expf(o2) * c_aw[bn];
            const float ph = __expf(o3) * c_ah[bn];

            const float tx = gx - (float)gi;
            const float ty = gy - (float)gj;
            const float tw = __logf(gw / c_aw[bn]);
            const float th = __logf(gh / c_ah[bn]);

            const float xlo = px - 0.5f * pw, xhi = px + 0.5f * pw;
            const float ylo = py - 0.5f * ph, yhi = py + 0.5f * ph;

            // tconf = IoU(gt, pred_at)
            const float iw = fminf(gx + 0.5f * gw, xhi) - fmaxf(gx - 0.5f * gw, xlo);
            const float ih = fminf(gy + 0.5f * gh, yhi) - fmaxf(gy - 0.5f * gh, ylo);
            const float ca = (iw > 0.f && ih > 0.f) ? iw * ih : 0.f;
            const float tconf = ca / (gw * gh + pw * ph - ca);

            const float conf = sigmoidf_(o4);

            // full-list over predicate: must equal the dense decision at this cell
            const float c1 = 0.6f * (pw * ph);
            bool over = false;
            for (int k = 0; k < nv; k++) {
                const float4 a4 = sA[k];
                const float iw2 = fminf(xhi, a4.y) - fmaxf(xlo, a4.x);
                const float ih2 = fminf(yhi, a4.w) - fmaxf(ylo, a4.z);
                if ((fminf(iw2, ih2) > 0.f) &&
                    (fmaf(1.6f, iw2 * ih2, -sbz[k]) > c1)) { over = true; break; }
            }

            double c = 0.0;
            const float dx = x - tx;   c += 0.5 * (double)(dx * dx);
            const float dy = y - ty;   c += 0.5 * (double)(dy * dy);
            const float dw = o2 - tw;  c += 0.5 * (double)(dw * dw);
            const float dh = o3 - th;  c += 0.5 * (double)(dh * dh);
            const float dc = conf - tconf;
            c += 2.5 * (double)(dc * dc);                 // 0.5 * OBJECT_SCALE
            if (!over) c -= (double)(0.5f * conf * conf); // cancel dense default term

            const float m = fmaxf(o5, o6);
            const float lse = m + __logf(__expf(o5 - m) + __expf(o6 - m));
            c += (double)(lse - (((int)tcls) == 0 ? o5 : o6));

            const float clr = sigmoidf_(o7);
            const float dl = clr - lr;
            c += 0.25 * (double)(dl * dl);

            atomicAdd(&s_acc, c);
        }
        __syncthreads();
        if (tid == 0) blockc = s_acc;
    }

    // ---- accumulate + fused finalize (done-counter) ----
    if (tid == 0) {
        atomicAdd(&g_acc, blockc);
        __threadfence();
        if (atomicAdd(&g_done, 1u) == TOTAL_BLOCKS - 1) {
            __threadfence();
            const double v = atomicAdd(&g_acc, 0.0);
            res[0] = (float)(v / (double)NB);
        }
    }
}

extern "C" void kernel_launch(void* const* d_in, const int* in_sizes, int n_in,
                              void* d_out, int out_size)
{
    const float* output = (const float*)d_in[0];
    const float* target = (const float*)d_in[1];
    float* res = (float*)d_out;

    init_kernel<<<1, 1>>>();
    fused_kernel<<<dim3(DENSE_BX + 1, NB), TPB>>>(output, target, res);
}